// round 8
// baseline (speedup 1.0000x reference)
#include <cuda_runtime.h>

#define THREADS 128
#define BWARPS 4

typedef unsigned long long ull;

// float offsets into dynamic smem
#define OFF_U    0                     // 4096 floats
#define OFF_W1   4096                  // 48 (4 rows x 12)
#define OFF_B1D  4144                  // 24 (10 dup pairs + pad)
#define OFF_B2D  4168                  // 40 (19 dup pairs + pad)
#define OFF_W2   4208                  // 200 (10 x 20, col 19 = 0)
#define OFF_STG  4408                  // BWARPS x 2432
#define SMEM_FLOATS (OFF_STG + BWARPS * 2432)
#define SMEM_BYTES (SMEM_FLOATS * 4)

__device__ __forceinline__ ull pack2(float lo, float hi) {
    ull r; asm("mov.b64 %0, {%1, %2};" : "=l"(r) : "f"(lo), "f"(hi)); return r;
}
__device__ __forceinline__ void unpack2(ull v, float& lo, float& hi) {
    asm("mov.b64 {%0, %1}, %2;" : "=f"(lo), "=f"(hi) : "l"(v));
}
__device__ __forceinline__ ull ffma2(ull a, ull b, ull c) {
    ull d; asm("fma.rn.f32x2 %0, %1, %2, %3;" : "=l"(d) : "l"(a), "l"(b), "l"(c)); return d;
}
__device__ __forceinline__ unsigned smem_u32(const void* p) {
    unsigned a;
    asm("{ .reg .u64 t; cvta.to.shared.u64 t, %1; cvt.u32.u64 %0, t; }" : "=r"(a) : "l"(p));
    return a;
}

__global__ void __launch_bounds__(THREADS, 4) edge_mlp_kernel(
    const float* __restrict__ src, const float* __restrict__ dst,
    const float* __restrict__ eat, const float* __restrict__ u,
    const int*   __restrict__ batch,
    const float* __restrict__ W1, const float* __restrict__ b1,
    const float* __restrict__ W2, const float* __restrict__ b2,
    float* __restrict__ out, int E, int B)
{
    extern __shared__ __align__(16) float sm[];
    float* u_s = sm + OFF_U;
    const float* W1s = sm + OFF_W1;
    const float* b1d = sm + OFF_B1D;
    const float* b2d = sm + OFF_B2D;
    const float* W2p = sm + OFF_W2;

    const int t = threadIdx.x;
    const int Bc = (B < 4096) ? B : 4096;

    for (int i = t; i < Bc; i += THREADS) u_s[i] = u[i];
    if (t < 48) { int f = t / 12, j = t % 12; sm[OFF_W1 + t] = (j < 10) ? W1[f * 10 + j] : 0.f; }
    if (t < 24) sm[OFF_B1D + t] = (t < 20) ? b1[t >> 1] : 0.f;
    if (t < 40) sm[OFF_B2D + t] = (t < 38) ? b2[t >> 1] : 0.f;
    for (int i = t; i < 200; i += THREADS) {
        int j = i / 20, k = i % 20;
        sm[OFF_W2 + i] = (k < 19) ? W2[j * 19 + k] : 0.f;
    }
    __syncthreads();

    const int warp = t >> 5, lane = t & 31;
    const int wg = blockIdx.x * BWARPS + warp;
    const int nw = gridDim.x * BWARPS;
    const int ntiles = (E + 127) >> 7;
    float* myst = sm + OFF_STG + warp * 2432;
    const unsigned myst_sa = smem_u32(myst);

    for (int tile = wg; tile < ntiles; tile += nw) {
        const int base = tile << 7;
        if (base + 128 <= E) {
            // Front-batch all loads: 4 edges/thread
            float sv[4], dv[4], av[4], uv[4];
            int iv[4];
#pragma unroll
            for (int q = 0; q < 4; q++) {
                const int e = base + q * 32 + lane;
                sv[q] = src[e]; dv[q] = dst[e]; av[q] = eat[e]; iv[q] = batch[e];
            }
#pragma unroll
            for (int q = 0; q < 4; q++)
                uv[q] = ((unsigned)iv[q] < (unsigned)Bc) ? u_s[iv[q]] : __ldg(&u[iv[q]]);

            // Edge-pair packed inputs
            ull pv[2][4];
#pragma unroll
            for (int pr = 0; pr < 2; pr++) {
                pv[pr][0] = pack2(sv[2 * pr], sv[2 * pr + 1]);
                pv[pr][1] = pack2(dv[2 * pr], dv[2 * pr + 1]);
                pv[pr][2] = pack2(av[2 * pr], av[2 * pr + 1]);
                pv[pr][3] = pack2(uv[2 * pr], uv[2 * pr + 1]);
            }

            // Layer 1: one weight pass, both edge pairs
            ull px[2][10];
#pragma unroll
            for (int jg = 0; jg < 5; jg++) {
                const ulonglong2 bb = *(const ulonglong2*)&b1d[jg * 4];
                px[0][2 * jg] = bb.x; px[0][2 * jg + 1] = bb.y;
                px[1][2 * jg] = bb.x; px[1][2 * jg + 1] = bb.y;
            }
#pragma unroll
            for (int f = 0; f < 4; f++) {
                const float4 wA = *(const float4*)&W1s[f * 12 + 0];
                const float4 wB = *(const float4*)&W1s[f * 12 + 4];
                const float4 wC = *(const float4*)&W1s[f * 12 + 8];
                const float wj[10] = {wA.x, wA.y, wA.z, wA.w, wB.x, wB.y, wB.z, wB.w, wC.x, wC.y};
#pragma unroll
                for (int j = 0; j < 10; j++) {
                    const ull w = pack2(wj[j], wj[j]);
                    px[0][j] = ffma2(pv[0][f], w, px[0][j]);
                    px[1][j] = ffma2(pv[1][f], w, px[1][j]);
                }
            }

            // ReLU in place
#pragma unroll
            for (int pr = 0; pr < 2; pr++)
#pragma unroll
                for (int j = 0; j < 10; j++) {
                    float a, b;
                    unpack2(px[pr][j], a, b);
                    px[pr][j] = pack2(fmaxf(a, 0.f), fmaxf(b, 0.f));
                }

            // Drain previous tile's bulk store before overwriting staging
            if (lane == 0) asm volatile("cp.async.bulk.wait_group.read 0;" ::: "memory");
            __syncwarp();

            // Layer 2: one weight pass, write staged results
#pragma unroll
            for (int kg = 0; kg < 5; kg++) {
                const int k0 = kg * 4;
                const ulonglong2 b01 = *(const ulonglong2*)&b2d[2 * k0];
                const ulonglong2 b23 = *(const ulonglong2*)&b2d[2 * k0 + 4];
                ull acc[2][4];
                acc[0][0] = b01.x; acc[0][1] = b01.y; acc[0][2] = b23.x; acc[0][3] = b23.y;
                acc[1][0] = b01.x; acc[1][1] = b01.y; acc[1][2] = b23.x; acc[1][3] = b23.y;
#pragma unroll
                for (int j = 0; j < 10; j++) {
                    const float4 w4 = *(const float4*)&W2p[j * 20 + k0];
                    const ull w0 = pack2(w4.x, w4.x), w1 = pack2(w4.y, w4.y);
                    const ull w2 = pack2(w4.z, w4.z), w3 = pack2(w4.w, w4.w);
                    acc[0][0] = ffma2(px[0][j], w0, acc[0][0]);
                    acc[0][1] = ffma2(px[0][j], w1, acc[0][1]);
                    acc[0][2] = ffma2(px[0][j], w2, acc[0][2]);
                    acc[0][3] = ffma2(px[0][j], w3, acc[0][3]);
                    acc[1][0] = ffma2(px[1][j], w0, acc[1][0]);
                    acc[1][1] = ffma2(px[1][j], w1, acc[1][1]);
                    acc[1][2] = ffma2(px[1][j], w2, acc[1][2]);
                    acc[1][3] = ffma2(px[1][j], w3, acc[1][3]);
                }
                const int kn = (kg < 4) ? 4 : 3;
#pragma unroll
                for (int pr = 0; pr < 2; pr++) {
                    const int r0 = lane + pr * 64, r1 = r0 + 32;
#pragma unroll
                    for (int m = 0; m < 4; m++) {
                        if (m < kn) {
                            float lo, hi;
                            unpack2(acc[pr][m], lo, hi);
                            myst[r0 * 19 + k0 + m] = lo;
                            myst[r1 * 19 + k0 + m] = hi;
                        }
                    }
                }
            }

            __syncwarp();
            // Async bulk store: 9728B smem -> gmem via TMA path (no LDS/STG round-trip)
            if (lane == 0) {
                asm volatile("fence.proxy.async.shared::cta;" ::: "memory");
                asm volatile(
                    "cp.async.bulk.global.shared::cta.bulk_group [%0], [%1], %2;"
                    :: "l"(out + (size_t)base * 19), "r"(myst_sa), "r"(2432 * 4)
                    : "memory");
                asm volatile("cp.async.bulk.commit_group;" ::: "memory");
            }
        } else {
            // Tail tile: scalar fallback
            for (int e = base + lane; e < E; e += 32) {
                float s = src[e], d = dst[e], a = eat[e];
                int bi = batch[e];
                float uu = ((unsigned)bi < (unsigned)Bc) ? u_s[bi] : __ldg(&u[bi]);
                float feat[4] = {s, d, a, uu};
                float h[10];
#pragma unroll
                for (int j = 0; j < 10; j++) {
                    float x = b1d[2 * j];
#pragma unroll
                    for (int f = 0; f < 4; f++) x = fmaf(feat[f], W1s[f * 12 + j], x);
                    h[j] = fmaxf(x, 0.f);
                }
#pragma unroll
                for (int k = 0; k < 19; k++) {
                    float acc = b2d[2 * k];
#pragma unroll
                    for (int j = 0; j < 10; j++) acc = fmaf(h[j], W2p[j * 20 + k], acc);
                    out[(size_t)e * 19 + k] = acc;
                }
            }
        }
    }

    // Drain any outstanding bulk store before exit
    if (lane == 0) asm volatile("cp.async.bulk.wait_group 0;" ::: "memory");
}

extern "C" void kernel_launch(void* const* d_in, const int* in_sizes, int n_in,
                              void* d_out, int out_size) {
    const float* src   = (const float*)d_in[0];
    const float* dst   = (const float*)d_in[1];
    const float* eat   = (const float*)d_in[2];
    const float* u     = (const float*)d_in[3];
    const int*   batch = (const int*)d_in[4];
    const float* W1    = (const float*)d_in[5];
    const float* b1    = (const float*)d_in[6];
    const float* W2    = (const float*)d_in[7];
    const float* b2    = (const float*)d_in[8];
    const int E = in_sizes[0];
    const int B = in_sizes[3];

    cudaFuncSetAttribute(edge_mlp_kernel,
                         cudaFuncAttributeMaxDynamicSharedMemorySize, SMEM_BYTES);

    edge_mlp_kernel<<<592, THREADS, SMEM_BYTES>>>(src, dst, eat, u, batch,
                                                  W1, b1, W2, b2, (float*)d_out, E, B);
}

// round 9
// speedup vs baseline: 1.0315x; 1.0315x over previous
#include <cuda_runtime.h>

#define THREADS 128
#define BWARPS 4

typedef unsigned long long ull;

// float offsets into dynamic smem
#define OFF_U    0                     // 4096 floats
#define OFF_W1   4096                  // 48 (4 rows x 12)
#define OFF_B1D  4144                  // 24 (10 dup pairs + pad)
#define OFF_B2D  4168                  // 40 (19 dup pairs + pad)
#define OFF_W2   4208                  // 200 (10 x 20, col 19 = 0)
#define OFF_STG  4408                  // BWARPS x 1216
#define SMEM_FLOATS (OFF_STG + BWARPS * 1216)
#define SMEM_BYTES (SMEM_FLOATS * 4)

__device__ __forceinline__ ull pack2(float lo, float hi) {
    ull r; asm("mov.b64 %0, {%1, %2};" : "=l"(r) : "f"(lo), "f"(hi)); return r;
}
__device__ __forceinline__ void unpack2(ull v, float& lo, float& hi) {
    asm("mov.b64 {%0, %1}, %2;" : "=f"(lo), "=f"(hi) : "l"(v));
}
__device__ __forceinline__ ull ffma2(ull a, ull b, ull c) {
    ull d; asm("fma.rn.f32x2 %0, %1, %2, %3;" : "=l"(d) : "l"(a), "l"(b), "l"(c)); return d;
}
__device__ __forceinline__ unsigned smem_u32(const void* p) {
    unsigned a;
    asm("{ .reg .u64 t; cvta.to.shared.u64 t, %1; cvt.u32.u64 %0, t; }" : "=r"(a) : "l"(p));
    return a;
}

__global__ void __launch_bounds__(THREADS, 6) edge_mlp_kernel(
    const float* __restrict__ src, const float* __restrict__ dst,
    const float* __restrict__ eat, const float* __restrict__ u,
    const int*   __restrict__ batch,
    const float* __restrict__ W1, const float* __restrict__ b1,
    const float* __restrict__ W2, const float* __restrict__ b2,
    float* __restrict__ out, int E, int B)
{
    extern __shared__ __align__(16) float sm[];
    float* u_s = sm + OFF_U;
    const float* W1s = sm + OFF_W1;
    const float* b1d = sm + OFF_B1D;
    const float* b2d = sm + OFF_B2D;
    const float* W2p = sm + OFF_W2;

    const int t = threadIdx.x;
    const int Bc = (B < 4096) ? B : 4096;

    for (int i = t; i < Bc; i += THREADS) u_s[i] = u[i];
    if (t < 48) { int f = t / 12, j = t % 12; sm[OFF_W1 + t] = (j < 10) ? W1[f * 10 + j] : 0.f; }
    if (t < 24) sm[OFF_B1D + t] = (t < 20) ? b1[t >> 1] : 0.f;
    if (t < 40) sm[OFF_B2D + t] = (t < 38) ? b2[t >> 1] : 0.f;
    for (int i = t; i < 200; i += THREADS) {
        int j = i / 20, k = i % 20;
        sm[OFF_W2 + i] = (k < 19) ? W2[j * 19 + k] : 0.f;
    }
    __syncthreads();

    const int warp = t >> 5, lane = t & 31;
    const int wg = blockIdx.x * BWARPS + warp;
    const int nw = gridDim.x * BWARPS;
    const int ntiles = (E + 63) >> 6;      // 64-edge tiles
    float* myst = sm + OFF_STG + warp * 1216;
    const unsigned myst_sa = smem_u32(myst);

    for (int tile = wg; tile < ntiles; tile += nw) {
        const int base = tile << 6;
        if (base + 64 <= E) {
            // 2 edges/thread: rows lane, lane+32
            const int e0 = base + lane, e1 = base + 32 + lane;
            const float s0 = src[e0], s1 = src[e1];
            const float d0 = dst[e0], d1 = dst[e1];
            const float a0 = eat[e0], a1 = eat[e1];
            const int i0 = batch[e0], i1 = batch[e1];
            const float u0 = ((unsigned)i0 < (unsigned)Bc) ? u_s[i0] : __ldg(&u[i0]);
            const float u1 = ((unsigned)i1 < (unsigned)Bc) ? u_s[i1] : __ldg(&u[i1]);

            // Edge-pair packed inputs: lo=edge e0, hi=edge e1
            ull pv[4];
            pv[0] = pack2(s0, s1);
            pv[1] = pack2(d0, d1);
            pv[2] = pack2(a0, a1);
            pv[3] = pack2(u0, u1);

            // Layer 1: px[j] = (x_e0[j], x_e1[j])
            ull px[10];
#pragma unroll
            for (int jg = 0; jg < 5; jg++) {
                const ulonglong2 bb = *(const ulonglong2*)&b1d[jg * 4];
                px[2 * jg] = bb.x; px[2 * jg + 1] = bb.y;
            }
#pragma unroll
            for (int f = 0; f < 4; f++) {
                const float4 wA = *(const float4*)&W1s[f * 12 + 0];
                const float4 wB = *(const float4*)&W1s[f * 12 + 4];
                const float4 wC = *(const float4*)&W1s[f * 12 + 8];
                const float wj[10] = {wA.x, wA.y, wA.z, wA.w, wB.x, wB.y, wB.z, wB.w, wC.x, wC.y};
#pragma unroll
                for (int j = 0; j < 10; j++) {
                    const ull w = pack2(wj[j], wj[j]);
                    px[j] = ffma2(pv[f], w, px[j]);
                }
            }

            // ReLU in place
#pragma unroll
            for (int j = 0; j < 10; j++) {
                float a, b;
                unpack2(px[j], a, b);
                px[j] = pack2(fmaxf(a, 0.f), fmaxf(b, 0.f));
            }

            // Drain previous tile's bulk store before overwriting staging
            if (lane == 0) asm volatile("cp.async.bulk.wait_group.read 0;" ::: "memory");
            __syncwarp();

            // Layer 2: 5 groups of 4 output columns
#pragma unroll
            for (int kg = 0; kg < 5; kg++) {
                const int k0 = kg * 4;
                const ulonglong2 b01 = *(const ulonglong2*)&b2d[2 * k0];
                const ulonglong2 b23 = *(const ulonglong2*)&b2d[2 * k0 + 4];
                ull acc0 = b01.x, acc1 = b01.y, acc2 = b23.x, acc3 = b23.y;
#pragma unroll
                for (int j = 0; j < 10; j++) {
                    const float4 w4 = *(const float4*)&W2p[j * 20 + k0];
                    acc0 = ffma2(px[j], pack2(w4.x, w4.x), acc0);
                    acc1 = ffma2(px[j], pack2(w4.y, w4.y), acc1);
                    acc2 = ffma2(px[j], pack2(w4.z, w4.z), acc2);
                    acc3 = ffma2(px[j], pack2(w4.w, w4.w), acc3);
                }
                const int kn = (kg < 4) ? 4 : 3;
                ull accs[4] = {acc0, acc1, acc2, acc3};
#pragma unroll
                for (int m = 0; m < 4; m++) {
                    if (m < kn) {
                        float lo, hi;
                        unpack2(accs[m], lo, hi);
                        myst[lane * 19 + k0 + m] = lo;          // edge e0
                        myst[(lane + 32) * 19 + k0 + m] = hi;   // edge e1
                    }
                }
            }

            __syncwarp();
            // Async bulk store: 4864B smem -> gmem (TMA path)
            if (lane == 0) {
                asm volatile("fence.proxy.async.shared::cta;" ::: "memory");
                asm volatile(
                    "cp.async.bulk.global.shared::cta.bulk_group [%0], [%1], %2;"
                    :: "l"(out + (size_t)base * 19), "r"(myst_sa), "r"(1216 * 4)
                    : "memory");
                asm volatile("cp.async.bulk.commit_group;" ::: "memory");
            }
        } else {
            // Tail tile: scalar fallback
            for (int e = base + lane; e < E; e += 32) {
                float s = src[e], d = dst[e], a = eat[e];
                int bi = batch[e];
                float uu = ((unsigned)bi < (unsigned)Bc) ? u_s[bi] : __ldg(&u[bi]);
                float feat[4] = {s, d, a, uu};
                float h[10];
#pragma unroll
                for (int j = 0; j < 10; j++) {
                    float x = b1d[2 * j];
#pragma unroll
                    for (int f = 0; f < 4; f++) x = fmaf(feat[f], W1s[f * 12 + j], x);
                    h[j] = fmaxf(x, 0.f);
                }
#pragma unroll
                for (int k = 0; k < 19; k++) {
                    float acc = b2d[2 * k];
#pragma unroll
                    for (int j = 0; j < 10; j++) acc = fmaf(h[j], W2p[j * 20 + k], acc);
                    out[(size_t)e * 19 + k] = acc;
                }
            }
        }
    }

    // Drain any outstanding bulk store before exit
    if (lane == 0) asm volatile("cp.async.bulk.wait_group 0;" ::: "memory");
}

extern "C" void kernel_launch(void* const* d_in, const int* in_sizes, int n_in,
                              void* d_out, int out_size) {
    const float* src   = (const float*)d_in[0];
    const float* dst   = (const float*)d_in[1];
    const float* eat   = (const float*)d_in[2];
    const float* u     = (const float*)d_in[3];
    const int*   batch = (const int*)d_in[4];
    const float* W1    = (const float*)d_in[5];
    const float* b1    = (const float*)d_in[6];
    const float* W2    = (const float*)d_in[7];
    const float* b2    = (const float*)d_in[8];
    const int E = in_sizes[0];
    const int B = in_sizes[3];

    cudaFuncSetAttribute(edge_mlp_kernel,
                         cudaFuncAttributeMaxDynamicSharedMemorySize, SMEM_BYTES);

    edge_mlp_kernel<<<888, THREADS, SMEM_BYTES>>>(src, dst, eat, u, batch,
                                                  W1, b1, W2, b2, (float*)d_out, E, B);
}